// round 1
// baseline (speedup 1.0000x reference)
#include <cuda_runtime.h>

#define BATCH 64
#define NIN   1024
#define DIN   512
#define NC    32
#define DC    64
#define ZDIM  2048   // NC*DC
#define EPSQ  1e-7f

// ---------------- scratch (device globals: allocation-free) ----------------
__device__ float g_ubar[BATCH*DIN];        // 128 KB
__device__ float g_out[BATCH*NC*DC];       // 512 KB
__device__ float g_v[BATCH*NC*DIN];        // 4 MB
__device__ float g_s[BATCH*NC*DIN];        // 4 MB

__global__ void zero_ubar_kernel(){
  int i = blockIdx.x*blockDim.x + threadIdx.x;
  if (i < BATCH*DIN) g_ubar[i] = 0.f;
}
__global__ void zero_s_kernel(){
  int i = blockIdx.x*blockDim.x + threadIdx.x;
  if (i < BATCH*NC*DIN) g_s[i] = 0.f;
}

// ubar[b,k] = sum_i u[b,i,k]   (4 i-partitions, atomic combine)
__global__ void colsum_kernel(const float* __restrict__ u){
  int b = blockIdx.x, part = blockIdx.y;
  int k = threadIdx.x;                          // 512 threads
  const float* up = u + ((size_t)b*NIN + (size_t)part*256)*DIN + k;
  float s = 0.f;
  #pragma unroll 8
  for (int i = 0; i < 256; ++i) s += up[(size_t)i*DIN];
  atomicAdd(&g_ubar[b*DIN + k], s);
}

// out[b,n,d] = squash_d( sum_k W[k, n*DC+d] * S[b,(n),k] )
// useUbar: S = g_ubar (broadcast over n), else S = g_s
// dstOpt: nullptr -> g_out, else final output buffer
__global__ void out_from_s_kernel(const float* __restrict__ W, int useUbar,
                                  float* __restrict__ dstOpt){
  int n    = blockIdx.x;
  int d    = threadIdx.x & 63;
  int ks   = threadIdx.x >> 6;    // 0..3 k-split
  int lane = threadIdx.x & 31;
  __shared__ float s_sm[DIN];
  __shared__ float red[4][DC];
  __shared__ float sq2[2];
  float* dst = dstOpt ? dstOpt : g_out;
  for (int bb = 0; bb < 8; ++bb){
    int b = blockIdx.y*8 + bb;
    const float* Sp = useUbar ? (g_ubar + (size_t)b*DIN)
                              : (g_s + ((size_t)b*NC + n)*DIN);
    for (int k = threadIdx.x; k < DIN; k += 256) s_sm[k] = Sp[k];
    __syncthreads();
    float acc = 0.f;
    const float* Wp = W + (size_t)(ks*128)*ZDIM + n*DC + d;
    #pragma unroll 8
    for (int k = 0; k < 128; ++k) acc += Wp[(size_t)k*ZDIM] * s_sm[ks*128 + k];
    red[ks][d] = acc;
    __syncthreads();
    if (ks == 0){
      float tot = red[0][d] + red[1][d] + red[2][d] + red[3][d];
      float sq = tot*tot;
      #pragma unroll
      for (int o = 16; o; o >>= 1) sq += __shfl_xor_sync(0xffffffffu, sq, o);
      if (lane == 0) sq2[d >> 5] = sq;
      red[0][d] = tot;
    }
    __syncthreads();
    if (ks == 0){
      float tot = red[0][d];
      float inv = rsqrtf(sq2[0] + sq2[1] + EPSQ);
      dst[((size_t)b*NC + n)*DC + d] = tot * inv;
    }
    __syncthreads();
  }
}

// v[b,n,k] = sum_d W[k, n*DC+d] * out[b,n,d]
__global__ void v_kernel(const float* __restrict__ W){
  int n  = blockIdx.x;
  int tg = threadIdx.x >> 3;   // 0..31 : k-row group
  int tl = threadIdx.x & 7;    // 0..7  : d-slice
  __shared__ float o_sm[DC];
  for (int bb = 0; bb < 8; ++bb){
    int b = blockIdx.y*8 + bb;
    if (threadIdx.x < DC)
      o_sm[threadIdx.x] = g_out[((size_t)b*NC + n)*DC + threadIdx.x];
    __syncthreads();
    #pragma unroll
    for (int kk = 0; kk < 16; ++kk){
      int k = kk*32 + tg;
      const float* Wp = W + (size_t)k*ZDIM + n*DC + tl*8;
      float a = 0.f;
      #pragma unroll
      for (int j = 0; j < 8; ++j) a += Wp[j]*o_sm[tl*8 + j];
      #pragma unroll
      for (int o = 4; o; o >>= 1) a += __shfl_down_sync(0xffffffffu, a, o, 8);
      if (tl == 0) g_v[((size_t)b*NC + n)*DIN + k] = a;
    }
    __syncthreads();
  }
}

// Fused routing pass: for each (b,i):
//   l[n] = v[b,n,:]·u[b,i,:];  c = softmax_n(l);  s[b,n,:] += c[n]*u[b,i,:]
// Grid: (BATCH, 8 i-chunks of 128). 256 threads = 8 warps; warp w owns
// capsules 4w..4w+3; lane owns k-slice {g*128 + lane*4 + j : g<4, j<4}.
#define SMEM_BYTES ((NC*DIN + 8*DIN + NC*8 + NC*8)*4)

__global__ void __launch_bounds__(256) routing_kernel(const float* __restrict__ u){
  extern __shared__ float sm[];
  float* v_s = sm;                 // 32*512
  float* u_s = sm + NC*DIN;        // 8*512
  float* l_s = u_s + 8*DIN;        // 32*8
  float* c_s = l_s + NC*8;         // 32*8

  int b    = blockIdx.x;
  int ic   = blockIdx.y;           // i chunk of 128
  int t    = threadIdx.x;
  int w    = t >> 5, lane = t & 31;
  int n0   = w*4;

  // stage v[b,:,:] into smem (64 KB, contiguous)
  {
    const float4* vg = (const float4*)(g_v + (size_t)b*NC*DIN);
    float4* v4 = (float4*)v_s;
    #pragma unroll
    for (int r = 0; r < 16; ++r) v4[r*256 + t] = vg[r*256 + t];
  }
  __syncthreads();

  // per-thread caches
  float vr[4][16];
  #pragma unroll
  for (int nn = 0; nn < 4; ++nn)
    #pragma unroll
    for (int g = 0; g < 4; ++g){
      float4 vv = *(const float4*)&v_s[(size_t)(n0+nn)*DIN + g*128 + lane*4];
      vr[nn][g*4+0] = vv.x; vr[nn][g*4+1] = vv.y;
      vr[nn][g*4+2] = vv.z; vr[nn][g*4+3] = vv.w;
    }

  float acc[4][16];
  #pragma unroll
  for (int nn = 0; nn < 4; ++nn)
    #pragma unroll
    for (int kk = 0; kk < 16; ++kk) acc[nn][kk] = 0.f;

  const float* ug = u + ((size_t)b*NIN + (size_t)ic*128)*DIN;

  for (int blk = 0; blk < 16; ++blk){
    // load 8 i-rows of u
    {
      const float4* ub = (const float4*)(ug + (size_t)blk*8*DIN);
      float4* u4 = (float4*)u_s;
      #pragma unroll
      for (int r = 0; r < 4; ++r) u4[r*256 + t] = ub[r*256 + t];
    }
    __syncthreads();

    // logits: p[nn][ib] = partial over this lane's 16 k
    float p[4][8];
    #pragma unroll
    for (int ib = 0; ib < 8; ++ib){
      float ur[16];
      #pragma unroll
      for (int g = 0; g < 4; ++g){
        float4 uu = *(const float4*)&u_s[ib*DIN + g*128 + lane*4];
        ur[g*4+0] = uu.x; ur[g*4+1] = uu.y; ur[g*4+2] = uu.z; ur[g*4+3] = uu.w;
      }
      #pragma unroll
      for (int nn = 0; nn < 4; ++nn){
        float s0 = 0.f;
        #pragma unroll
        for (int kk = 0; kk < 16; ++kk) s0 += vr[nn][kk]*ur[kk];
        p[nn][ib] = s0;
      }
    }
    // full cross-lane reduction of all 32 partial dots
    #pragma unroll
    for (int nn = 0; nn < 4; ++nn)
      #pragma unroll
      for (int ib = 0; ib < 8; ++ib)
        #pragma unroll
        for (int o = 16; o; o >>= 1)
          p[nn][ib] += __shfl_xor_sync(0xffffffffu, p[nn][ib], o);
    // one lane per (nn,ib) publishes
    #pragma unroll
    for (int ib = 0; ib < 8; ++ib)
      #pragma unroll
      for (int nn = 0; nn < 4; ++nn)
        if (lane == ib*4 + nn) l_s[(n0+nn)*8 + ib] = p[nn][ib];
    __syncthreads();

    // softmax over capsules: warp w handles ib = w; lane = capsule index
    {
      float lv = l_s[lane*8 + w];
      float M = lv;
      #pragma unroll
      for (int o = 16; o; o >>= 1) M = fmaxf(M, __shfl_xor_sync(0xffffffffu, M, o));
      float e = __expf(lv - M);
      float S = e;
      #pragma unroll
      for (int o = 16; o; o >>= 1) S += __shfl_xor_sync(0xffffffffu, S, o);
      c_s[lane*8 + w] = e / S;
    }
    __syncthreads();

    // accumulate s += c[n] * u_i
    #pragma unroll
    for (int ib = 0; ib < 8; ++ib){
      float cr[4];
      #pragma unroll
      for (int nn = 0; nn < 4; ++nn) cr[nn] = c_s[(n0+nn)*8 + ib];
      float ur[16];
      #pragma unroll
      for (int g = 0; g < 4; ++g){
        float4 uu = *(const float4*)&u_s[ib*DIN + g*128 + lane*4];
        ur[g*4+0] = uu.x; ur[g*4+1] = uu.y; ur[g*4+2] = uu.z; ur[g*4+3] = uu.w;
      }
      #pragma unroll
      for (int nn = 0; nn < 4; ++nn)
        #pragma unroll
        for (int kk = 0; kk < 16; ++kk)
          acc[nn][kk] += cr[nn]*ur[kk];
    }
    __syncthreads();   // before next u_s overwrite
  }

  // flush accumulators (8 partial CTAs per address)
  #pragma unroll
  for (int nn = 0; nn < 4; ++nn){
    float* sp = g_s + ((size_t)b*NC + (n0+nn))*DIN;
    #pragma unroll
    for (int g = 0; g < 4; ++g)
      #pragma unroll
      for (int j = 0; j < 4; ++j)
        atomicAdd(&sp[g*128 + lane*4 + j], acc[nn][g*4+j]);
  }
}

// --------------------------------------------------------------------------
extern "C" void kernel_launch(void* const* d_in, const int* in_sizes, int n_in,
                              void* d_out, int out_size){
  const float* u = (const float*)d_in[0];   // [64,1024,512]
  const float* W = (const float*)d_in[1];   // [1,512,2048]
  float* out = (float*)d_out;               // [64,32,64]
  (void)in_sizes; (void)n_in; (void)out_size;

  cudaFuncSetAttribute(routing_kernel,
                       cudaFuncAttributeMaxDynamicSharedMemorySize, SMEM_BYTES);

  // iter 0: uniform coupling -> out0 = squash(W_n^T * sum_i u_i)
  zero_ubar_kernel<<<(BATCH*DIN + 255)/256, 256>>>();
  colsum_kernel<<<dim3(BATCH, 4), 512>>>(u);
  out_from_s_kernel<<<dim3(NC, 8), 256>>>(W, /*useUbar=*/1, nullptr);

  // iters 1,2: fused logits+softmax+accumulate pass over u
  for (int iter = 0; iter < 2; ++iter){
    v_kernel<<<dim3(NC, 8), 256>>>(W);
    zero_s_kernel<<<(BATCH*NC*DIN + 255)/256, 256>>>();
    routing_kernel<<<dim3(BATCH, 8), 256, SMEM_BYTES>>>(u);
    out_from_s_kernel<<<dim3(NC, 8), 256>>>(W, /*useUbar=*/0,
                                            iter == 1 ? out : nullptr);
  }
}

// round 2
// speedup vs baseline: 1.4313x; 1.4313x over previous
#include <cuda_runtime.h>

#define BATCH 64
#define NIN   1024
#define DIN   512
#define NC    32
#define DC    64
#define ZDIM  2048   // NC*DC
#define EPSQ  1e-7f
#define ICN   4              // i-chunks (routing partials)
#define IPC   (NIN/ICN)      // 256 i per routing CTA
#define BG    16             // batches per outv CTA
#define NBG   (BATCH/BG)     // 4
#define WPAD  68             // padded W row stride (floats) in smem
#define RB    16             // i-rows per routing block-iter

typedef unsigned long long u64;

// ---------------- scratch (device globals: allocation-free) ----------------
__device__ __align__(16) float g_cspart[ICN*BATCH*DIN];            // 512 KB
__device__ __align__(16) float g_spart[(size_t)ICN*BATCH*NC*DIN];  // 16 MB
__device__ __align__(16) float g_v[BATCH*NC*DIN];                  // 4 MB

// ---------------- f32x2 packed helpers (sm_100+) ----------------
__device__ __forceinline__ u64 fma2(u64 a, u64 b, u64 c){
  u64 d; asm("fma.rn.f32x2 %0, %1, %2, %3;" : "=l"(d) : "l"(a), "l"(b), "l"(c));
  return d;
}
__device__ __forceinline__ u64 add2(u64 a, u64 b){
  u64 d; asm("add.rn.f32x2 %0, %1, %2;" : "=l"(d) : "l"(a), "l"(b));
  return d;
}
__device__ __forceinline__ float hadd2(u64 v){
  float lo, hi; asm("mov.b64 {%0, %1}, %2;" : "=f"(lo), "=f"(hi) : "l"(v));
  return lo + hi;
}
__device__ __forceinline__ u64 dup2(float x){
  u64 v; asm("mov.b64 %0, {%1, %2};" : "=l"(v) : "f"(x), "f"(x));
  return v;
}

// ---------------- colsum: g_cspart[p][b][k] = sum over i-chunk p of u[b,i,k]
__global__ void __launch_bounds__(512) colsum_kernel(const float* __restrict__ u){
  int b = blockIdx.x, part = blockIdx.y, k = threadIdx.x;
  const float* up = u + ((size_t)b*NIN + (size_t)part*IPC)*DIN + k;
  float s = 0.f;
  #pragma unroll 8
  for (int i = 0; i < IPC; ++i) s += up[(size_t)i*DIN];
  g_cspart[(part*BATCH + b)*DIN + k] = s;
}

// ---------------- outv: out[b,n,:] = squash(W_n^T s[b,n,:]);  v[b,n,:] = W_n out
// mode 0: s = sum of 4 colsum partials (iter-0 uniform coupling, 1/32 cancels in squash)
// mode 1: s = sum of 4 routing partials
// doV=0: skip v phase (final iteration); outF != nullptr -> also write out there
#define OUTV_SMEM ((DIN*WPAD + BG*DIN + BG*DC + BG*2)*4)

__global__ void __launch_bounds__(256,1) outv_kernel(
    const float* __restrict__ W, int mode, int doV, float* __restrict__ outF){
  extern __shared__ __align__(16) float sm[];
  float* W_s  = sm;                    // [512][68]
  float* s_s  = W_s + DIN*WPAD;        // [16][512]
  float* o_s  = s_s + BG*DIN;          // [16][64]
  float* sq_s = o_s + BG*DC;           // [16][2]
  int n = blockIdx.x, bg = blockIdx.y, t = threadIdx.x;

  // stage W_n (k-major, padded rows)
  for (int m = t; m < DIN*DC/4; m += 256){
    int k = m >> 4, q = m & 15;
    *(float4*)&W_s[k*WPAD + q*4] =
        *(const float4*)(W + (size_t)k*ZDIM + n*DC + q*4);
  }
  // stage s (sum 4 partial buffers)
  for (int m = t; m < BG*DIN/4; m += 256){
    int b = m >> 7, f = (m & 127)*4;
    int gb = bg*BG + b;
    float4 a0, a1, a2, a3;
    if (mode == 0){
      a0 = *(const float4*)&g_cspart[(0*BATCH+gb)*DIN + f];
      a1 = *(const float4*)&g_cspart[(1*BATCH+gb)*DIN + f];
      a2 = *(const float4*)&g_cspart[(2*BATCH+gb)*DIN + f];
      a3 = *(const float4*)&g_cspart[(3*BATCH+gb)*DIN + f];
    } else {
      a0 = *(const float4*)&g_spart[(((size_t)0*BATCH+gb)*NC + n)*DIN + f];
      a1 = *(const float4*)&g_spart[(((size_t)1*BATCH+gb)*NC + n)*DIN + f];
      a2 = *(const float4*)&g_spart[(((size_t)2*BATCH+gb)*NC + n)*DIN + f];
      a3 = *(const float4*)&g_spart[(((size_t)3*BATCH+gb)*NC + n)*DIN + f];
    }
    float4 r;
    r.x = a0.x+a1.x+a2.x+a3.x; r.y = a0.y+a1.y+a2.y+a3.y;
    r.z = a0.z+a1.z+a2.z+a3.z; r.w = a0.w+a1.w+a2.w+a3.w;
    *(float4*)&s_s[b*DIN + f] = r;
  }
  __syncthreads();

  // ---- out phase: thread (d = t&63, bq = t>>6), 4 b per thread
  int d = t & 63, bq = t >> 6, lane = t & 31;
  float acc[4] = {0.f, 0.f, 0.f, 0.f};
  for (int kb = 0; kb < DIN; kb += 4){
    float w0 = W_s[(kb+0)*WPAD + d];
    float w1 = W_s[(kb+1)*WPAD + d];
    float w2 = W_s[(kb+2)*WPAD + d];
    float w3 = W_s[(kb+3)*WPAD + d];
    #pragma unroll
    for (int j = 0; j < 4; ++j){
      float4 sv = *(const float4*)&s_s[(bq*4+j)*DIN + kb];
      acc[j] += w0*sv.x + w1*sv.y + w2*sv.z + w3*sv.w;
    }
  }
  int half = d >> 5;
  #pragma unroll
  for (int j = 0; j < 4; ++j){
    float sq = acc[j]*acc[j];
    #pragma unroll
    for (int o = 16; o; o >>= 1) sq += __shfl_xor_sync(0xffffffffu, sq, o);
    if (lane == 0) sq_s[(bq*4+j)*2 + half] = sq;
  }
  __syncthreads();
  #pragma unroll
  for (int j = 0; j < 4; ++j){
    int b = bq*4 + j;
    float inv = rsqrtf(sq_s[b*2] + sq_s[b*2+1] + EPSQ);
    float o = acc[j]*inv;
    o_s[b*DC + d] = o;
    if (outF) outF[((size_t)(bg*BG+b)*NC + n)*DC + d] = o;
  }
  if (!doV) return;
  __syncthreads();

  // ---- v phase: thread owns k = t and k+256; W row cached in regs (f32x2)
  #pragma unroll
  for (int kk = 0; kk < 2; ++kk){
    int k = t + kk*256;
    u64 wr[32];
    #pragma unroll
    for (int q = 0; q < 16; ++q){
      ulonglong2 wv = *(const ulonglong2*)&W_s[k*WPAD + q*4];
      wr[q*2] = wv.x; wr[q*2+1] = wv.y;
    }
    #pragma unroll 2
    for (int b = 0; b < BG; ++b){
      u64 a0 = 0ull, a1 = 0ull;
      const ulonglong2* ob = (const ulonglong2*)&o_s[b*DC];
      #pragma unroll
      for (int q = 0; q < 16; ++q){
        ulonglong2 ov = ob[q];
        a0 = fma2(wr[q*2],   ov.x, a0);
        a1 = fma2(wr[q*2+1], ov.y, a1);
      }
      g_v[((size_t)(bg*BG+b)*NC + n)*DIN + k] = hadd2(add2(a0, a1));
    }
  }
}

// ---------------- routing: per (b,i): l[n]=v[b,n,:]·u_i; c=softmax_n(l);
//                  spart[ic][b,n,:] += c[n]*u_i
// 512 threads = 16 warps; warp w owns capsules {2w,2w+1}; lane owns 16 k
// (k = g*128 + lane*4 + j). f32x2 throughout.
__global__ void __launch_bounds__(512,1) routing_kernel(const float* __restrict__ u){
  __shared__ __align__(16) float u_s[RB*DIN];   // 32 KB
  __shared__ float l_s[NC*RB];
  __shared__ float c_s[NC*RB];
  int b = blockIdx.x, ic = blockIdx.y;
  int t = threadIdx.x, w = t >> 5, lane = t & 31;
  int n0 = w*2;

  u64 vr2[2][8];
  #pragma unroll
  for (int nn = 0; nn < 2; ++nn)
    #pragma unroll
    for (int g = 0; g < 4; ++g){
      ulonglong2 vv = *(const ulonglong2*)
          &g_v[((size_t)b*NC + n0+nn)*DIN + g*128 + lane*4];
      vr2[nn][g*2] = vv.x; vr2[nn][g*2+1] = vv.y;
    }
  u64 acc2[2][8];
  #pragma unroll
  for (int nn = 0; nn < 2; ++nn)
    #pragma unroll
    for (int kk = 0; kk < 8; ++kk) acc2[nn][kk] = 0ull;

  const float* ug = u + ((size_t)b*NIN + (size_t)ic*IPC)*DIN;

  for (int blk = 0; blk < IPC/RB; ++blk){          // 16 iters of 16 i-rows
    {
      const float4* ub = (const float4*)(ug + (size_t)blk*RB*DIN);
      float4* u4 = (float4*)u_s;
      #pragma unroll
      for (int r = 0; r < 4; ++r) u4[r*512 + t] = ub[r*512 + t];
    }
    __syncthreads();

    // logits (two halves of 8 i each; publish immediately, no barrier between)
    #pragma unroll
    for (int h = 0; h < 2; ++h){
      float p[2][8];
      #pragma unroll
      for (int ibq = 0; ibq < 8; ++ibq){
        int ib = h*8 + ibq;
        u64 ur2[8];
        #pragma unroll
        for (int g = 0; g < 4; ++g){
          ulonglong2 uu = *(const ulonglong2*)&u_s[ib*DIN + g*128 + lane*4];
          ur2[g*2] = uu.x; ur2[g*2+1] = uu.y;
        }
        #pragma unroll
        for (int nn = 0; nn < 2; ++nn){
          u64 a0 = 0ull, a1 = 0ull;
          #pragma unroll
          for (int q = 0; q < 4; ++q){
            a0 = fma2(vr2[nn][q*2],   ur2[q*2],   a0);
            a1 = fma2(vr2[nn][q*2+1], ur2[q*2+1], a1);
          }
          p[nn][ibq] = hadd2(add2(a0, a1));
        }
      }
      #pragma unroll
      for (int nn = 0; nn < 2; ++nn)
        #pragma unroll
        for (int ibq = 0; ibq < 8; ++ibq)
          #pragma unroll
          for (int o = 16; o; o >>= 1)
            p[nn][ibq] += __shfl_xor_sync(0xffffffffu, p[nn][ibq], o);
      #pragma unroll
      for (int ibq = 0; ibq < 8; ++ibq)
        #pragma unroll
        for (int nn = 0; nn < 2; ++nn)
          if (lane == ibq*2 + nn)
            l_s[(n0+nn)*RB + h*8 + ibq] = p[nn][ibq];
    }
    __syncthreads();

    // softmax over capsules: warp w handles i-row ib = w; lane = capsule
    {
      float lv = l_s[lane*RB + w];
      float M = lv;
      #pragma unroll
      for (int o = 16; o; o >>= 1)
        M = fmaxf(M, __shfl_xor_sync(0xffffffffu, M, o));
      float e = __expf(lv - M);
      float S = e;
      #pragma unroll
      for (int o = 16; o; o >>= 1) S += __shfl_xor_sync(0xffffffffu, S, o);
      c_s[lane*RB + w] = e / S;
    }
    __syncthreads();

    // accumulate s += c[n] * u_i
    #pragma unroll 2
    for (int ib = 0; ib < RB; ++ib){
      u64 ur2[8];
      #pragma unroll
      for (int g = 0; g < 4; ++g){
        ulonglong2 uu = *(const ulonglong2*)&u_s[ib*DIN + g*128 + lane*4];
        ur2[g*2] = uu.x; ur2[g*2+1] = uu.y;
      }
      u64 c0 = dup2(c_s[(n0+0)*RB + ib]);
      u64 c1 = dup2(c_s[(n0+1)*RB + ib]);
      #pragma unroll
      for (int kk = 0; kk < 8; ++kk){
        acc2[0][kk] = fma2(c0, ur2[kk], acc2[0][kk]);
        acc2[1][kk] = fma2(c1, ur2[kk], acc2[1][kk]);
      }
    }
    __syncthreads();
  }

  // store partial s (disjoint per ic -> plain stores, no atomics)
  float* sp = g_spart + (((size_t)ic*BATCH + b)*NC + n0)*DIN;
  #pragma unroll
  for (int nn = 0; nn < 2; ++nn)
    #pragma unroll
    for (int g = 0; g < 4; ++g){
      ulonglong2 vv; vv.x = acc2[nn][g*2]; vv.y = acc2[nn][g*2+1];
      *(ulonglong2*)&sp[nn*DIN + g*128 + lane*4] = vv;
    }
}

// --------------------------------------------------------------------------
extern "C" void kernel_launch(void* const* d_in, const int* in_sizes, int n_in,
                              void* d_out, int out_size){
  const float* u = (const float*)d_in[0];   // [64,1024,512]
  const float* W = (const float*)d_in[1];   // [1,512,2048]
  float* out = (float*)d_out;               // [64,32,64]
  (void)in_sizes; (void)n_in; (void)out_size;

  cudaFuncSetAttribute(outv_kernel,
                       cudaFuncAttributeMaxDynamicSharedMemorySize, OUTV_SMEM);

  // iter 0: uniform coupling -> out0 = squash(W_n^T sum_i u_i), then v0
  colsum_kernel<<<dim3(BATCH, ICN), 512>>>(u);
  outv_kernel<<<dim3(NC, NBG), 256, OUTV_SMEM>>>(W, 0, 1, nullptr);

  // iter 1
  routing_kernel<<<dim3(BATCH, ICN), 512>>>(u);
  outv_kernel<<<dim3(NC, NBG), 256, OUTV_SMEM>>>(W, 1, 1, nullptr);

  // iter 2 (final: no v needed, write d_out)
  routing_kernel<<<dim3(BATCH, ICN), 512>>>(u);
  outv_kernel<<<dim3(NC, NBG), 256, OUTV_SMEM>>>(W, 1, 0, out);
}

// round 3
// speedup vs baseline: 3.1677x; 2.2131x over previous
#include <cuda_runtime.h>

#define BATCH 64
#define NIN   1024
#define DIN   512
#define NC    32
#define DC    64
#define ZDIM  2048   // NC*DC
#define EPSQ  1e-7f
#define ICN   4              // i-chunks
#define IPC   256            // i per logits/accum CTA
#define BG    16             // batches per outv CTA
#define NBG   (BATCH/BG)
#define WPAD  68
#define KC    32             // logits k-chunk
#define IPAD  261            // u_s row pad in logits ([k][i])
#define VPAD  36             // v_s row pad in logits ([k][n])
#define CPAD  34             // c_s row pad in accum  ([i][n])

typedef unsigned long long u64;

// ---------------- scratch ----------------
__device__ __align__(16) float g_cspart[ICN*BATCH*DIN];            // 512 KB
__device__ __align__(16) float g_spart[(size_t)ICN*BATCH*NC*DIN];  // 16 MB
__device__ __align__(16) float g_v[BATCH*NC*DIN];                  // 4 MB
__device__ __align__(16) float g_L[(size_t)BATCH*NC*NIN];          // 8 MB

// ---------------- f32x2 helpers ----------------
__device__ __forceinline__ u64 fma2(u64 a, u64 b, u64 c){
  u64 d; asm("fma.rn.f32x2 %0, %1, %2, %3;" : "=l"(d) : "l"(a), "l"(b), "l"(c));
  return d;
}
__device__ __forceinline__ u64 add2(u64 a, u64 b){
  u64 d; asm("add.rn.f32x2 %0, %1, %2;" : "=l"(d) : "l"(a), "l"(b));
  return d;
}
__device__ __forceinline__ float hadd2(u64 v){
  float lo, hi; asm("mov.b64 {%0, %1}, %2;" : "=f"(lo), "=f"(hi) : "l"(v));
  return lo + hi;
}
__device__ __forceinline__ u64 dup2(float x){
  u64 v; asm("mov.b64 %0, {%1, %2};" : "=l"(v) : "f"(x), "f"(x));
  return v;
}
__device__ __forceinline__ void unpk2(u64 v, float& lo, float& hi){
  asm("mov.b64 {%0, %1}, %2;" : "=f"(lo), "=f"(hi) : "l"(v));
}

// ---------------- colsum ----------------
__global__ void __launch_bounds__(512) colsum_kernel(const float* __restrict__ u){
  int b = blockIdx.x, part = blockIdx.y, k = threadIdx.x;
  const float* up = u + ((size_t)b*NIN + (size_t)part*IPC)*DIN + k;
  float s = 0.f;
  #pragma unroll 8
  for (int i = 0; i < IPC; ++i) s += up[(size_t)i*DIN];
  g_cspart[(part*BATCH + b)*DIN + k] = s;
}

// ---------------- outv: out = squash(W^T s); v = W out  (512 threads)
#define OUTV_SMEM ((DIN*WPAD + BG*DIN + BG*DC + BG*2)*4)

__global__ void __launch_bounds__(512,1) outv_kernel(
    const float* __restrict__ W, int mode, int doV, float* __restrict__ outF){
  extern __shared__ __align__(16) float sm[];
  float* W_s  = sm;                    // [512][68]
  float* s_s  = W_s + DIN*WPAD;        // [16][512]
  float* o_s  = s_s + BG*DIN;          // [16][64]
  float* sq_s = o_s + BG*DC;           // [16][2]
  int n = blockIdx.x, bg = blockIdx.y, t = threadIdx.x;

  for (int m = t; m < DIN*DC/4; m += 512){
    int k = m >> 4, q = m & 15;
    *(float4*)&W_s[k*WPAD + q*4] =
        *(const float4*)(W + (size_t)k*ZDIM + n*DC + q*4);
  }
  for (int m = t; m < BG*DIN/4; m += 512){
    int b = m >> 7, f = (m & 127)*4;
    int gb = bg*BG + b;
    float4 a0, a1, a2, a3;
    if (mode == 0){
      a0 = *(const float4*)&g_cspart[(0*BATCH+gb)*DIN + f];
      a1 = *(const float4*)&g_cspart[(1*BATCH+gb)*DIN + f];
      a2 = *(const float4*)&g_cspart[(2*BATCH+gb)*DIN + f];
      a3 = *(const float4*)&g_cspart[(3*BATCH+gb)*DIN + f];
    } else {
      a0 = *(const float4*)&g_spart[(((size_t)0*BATCH+gb)*NC + n)*DIN + f];
      a1 = *(const float4*)&g_spart[(((size_t)1*BATCH+gb)*NC + n)*DIN + f];
      a2 = *(const float4*)&g_spart[(((size_t)2*BATCH+gb)*NC + n)*DIN + f];
      a3 = *(const float4*)&g_spart[(((size_t)3*BATCH+gb)*NC + n)*DIN + f];
    }
    float4 r;
    r.x = a0.x+a1.x+a2.x+a3.x; r.y = a0.y+a1.y+a2.y+a3.y;
    r.z = a0.z+a1.z+a2.z+a3.z; r.w = a0.w+a1.w+a2.w+a3.w;
    *(float4*)&s_s[b*DIN + f] = r;
  }
  __syncthreads();

  // out phase: d = t&63, bq = t>>6 (0..7), 2 b each
  int d = t & 63, bq = t >> 6, lane = t & 31;
  float acc[2] = {0.f, 0.f};
  for (int kb = 0; kb < DIN; kb += 4){
    float w0 = W_s[(kb+0)*WPAD + d];
    float w1 = W_s[(kb+1)*WPAD + d];
    float w2 = W_s[(kb+2)*WPAD + d];
    float w3 = W_s[(kb+3)*WPAD + d];
    #pragma unroll
    for (int j = 0; j < 2; ++j){
      float4 sv = *(const float4*)&s_s[(bq*2+j)*DIN + kb];
      acc[j] += w0*sv.x + w1*sv.y + w2*sv.z + w3*sv.w;
    }
  }
  int half = d >> 5;
  #pragma unroll
  for (int j = 0; j < 2; ++j){
    float sq = acc[j]*acc[j];
    #pragma unroll
    for (int o = 16; o; o >>= 1) sq += __shfl_xor_sync(0xffffffffu, sq, o);
    if (lane == 0) sq_s[(bq*2+j)*2 + half] = sq;
  }
  __syncthreads();
  #pragma unroll
  for (int j = 0; j < 2; ++j){
    int b = bq*2 + j;
    float inv = rsqrtf(sq_s[b*2] + sq_s[b*2+1] + EPSQ);
    float o = acc[j]*inv;
    o_s[b*DC + d] = o;
    if (outF) outF[((size_t)(bg*BG+b)*NC + n)*DC + d] = o;
  }
  if (!doV) return;
  __syncthreads();

  // v phase: k = t (0..511); W row cached (f32x2)
  {
    int k = t;
    u64 wr[32];
    #pragma unroll
    for (int q = 0; q < 16; ++q){
      ulonglong2 wv = *(const ulonglong2*)&W_s[k*WPAD + q*4];
      wr[q*2] = wv.x; wr[q*2+1] = wv.y;
    }
    #pragma unroll 2
    for (int b = 0; b < BG; ++b){
      u64 a0 = 0ull, a1 = 0ull;
      const ulonglong2* ob = (const ulonglong2*)&o_s[b*DC];
      #pragma unroll
      for (int q = 0; q < 16; ++q){
        ulonglong2 ov = ob[q];
        a0 = fma2(wr[q*2],   ov.x, a0);
        a1 = fma2(wr[q*2+1], ov.y, a1);
      }
      g_v[((size_t)(bg*BG+b)*NC + n)*DIN + k] = hadd2(add2(a0, a1));
    }
  }
}

// ---------------- logits: L[b,n,i] = v[b,n,:]·u[b,i,:]
// 256 thr, warp w: n-oct n0=(w&3)*8, i-half h=w>>2; lane owns i = h*128+j*32+l.
__global__ void __launch_bounds__(256,2) logits_kernel(const float* __restrict__ u){
  __shared__ __align__(16) float u_s[KC*IPAD];   // [k][i]
  __shared__ __align__(8)  float v_s[KC*VPAD];   // [k][n]
  int b = blockIdx.x, ic = blockIdx.y;
  int t = threadIdx.x, w = t >> 5, l = t & 31;
  int n0 = (w & 3)*8, h = w >> 2;
  const float* ug = u + ((size_t)b*NIN + (size_t)ic*IPC)*DIN;
  const float* vg = g_v + (size_t)b*NC*DIN;

  u64 acc[4][4];
  #pragma unroll
  for (int p = 0; p < 4; ++p)
    #pragma unroll
    for (int j = 0; j < 4; ++j) acc[p][j] = 0ull;

  for (int kb = 0; kb < DIN; kb += KC){
    if (kb) __syncthreads();
    // stage u transposed: [k][i], pad 261 (conflict-free for this mapping)
    #pragma unroll
    for (int r = 0; r < 8; ++r){
      int m = r*256 + t;
      int i = m >> 3, kq = m & 7;
      float4 xv = *(const float4*)(ug + (size_t)i*DIN + kb + kq*4);
      u_s[(kq*4+0)*IPAD + i] = xv.x;
      u_s[(kq*4+1)*IPAD + i] = xv.y;
      u_s[(kq*4+2)*IPAD + i] = xv.z;
      u_s[(kq*4+3)*IPAD + i] = xv.w;
    }
    // stage v transposed: [k][n]
    {
      int n = t >> 3, kq = t & 7;
      float4 xv = *(const float4*)(vg + (size_t)n*DIN + kb + kq*4);
      v_s[(kq*4+0)*VPAD + n] = xv.x;
      v_s[(kq*4+1)*VPAD + n] = xv.y;
      v_s[(kq*4+2)*VPAD + n] = xv.z;
      v_s[(kq*4+3)*VPAD + n] = xv.w;
    }
    __syncthreads();
    #pragma unroll
    for (int k = 0; k < KC; ++k){
      u64 vv[4];
      #pragma unroll
      for (int p = 0; p < 4; ++p)
        vv[p] = *(const u64*)&v_s[k*VPAD + n0 + p*2];   // warp-uniform bcast
      #pragma unroll
      for (int j = 0; j < 4; ++j){
        u64 u2 = dup2(u_s[k*IPAD + h*128 + j*32 + l]);
        #pragma unroll
        for (int p = 0; p < 4; ++p) acc[p][j] = fma2(vv[p], u2, acc[p][j]);
      }
    }
  }
  float* Lg = g_L + (size_t)b*NC*NIN + (size_t)ic*IPC;
  #pragma unroll
  for (int p = 0; p < 4; ++p)
    #pragma unroll
    for (int j = 0; j < 4; ++j){
      float lo, hi; unpk2(acc[p][j], lo, hi);
      int i = h*128 + j*32 + l;
      Lg[(size_t)(n0+2*p  )*NIN + i] = lo;
      Lg[(size_t)(n0+2*p+1)*NIN + i] = hi;
    }
}

// ---------------- accum: c = softmax_n(L); spart[ic][b,n,:] += c[n]*u_i
// 256 thr, warp w: n-oct n0=(w&3)*8, k-half h=w>>2; lane owns k = h*256+j*32+l.
#define ACC_SMEM ((16*DIN + IPC*CPAD)*4)

__global__ void __launch_bounds__(256,2) accum_kernel(const float* __restrict__ u){
  extern __shared__ __align__(16) float asm_[];
  float* u_s = asm_;                 // [16][512]
  float* c_s = asm_ + 16*DIN;        // [256][34]
  int b = blockIdx.x, ic = blockIdx.y;
  int t = threadIdx.x, w = t >> 5, l = t & 31;
  int n0 = (w & 3)*8, h = w >> 2;

  // phase 1: softmax over capsules for column i = ic*IPC + t
  {
    const float* Lg = g_L + (size_t)b*NC*NIN + (size_t)ic*IPC + t;
    float x[NC];
    float M = -1e30f;
    #pragma unroll
    for (int n = 0; n < NC; ++n){
      x[n] = Lg[(size_t)n*NIN];
      M = fmaxf(M, x[n]);
    }
    float S = 0.f;
    #pragma unroll
    for (int n = 0; n < NC; ++n){ x[n] = __expf(x[n] - M); S += x[n]; }
    float inv = 1.0f / S;
    #pragma unroll
    for (int n = 0; n < NC; ++n) c_s[t*CPAD + n] = x[n]*inv;
  }

  u64 acc[4][8];
  #pragma unroll
  for (int p = 0; p < 4; ++p)
    #pragma unroll
    for (int j = 0; j < 8; ++j) acc[p][j] = 0ull;

  const float* ug = u + ((size_t)b*NIN + (size_t)ic*IPC)*DIN;
  for (int blk = 0; blk < 16; ++blk){
    __syncthreads();
    #pragma unroll
    for (int r = 0; r < 8; ++r){
      int m = r*256 + t;
      int i = m >> 7, f = (m & 127)*4;
      *(float4*)&u_s[i*DIN + f] =
          *(const float4*)(ug + (size_t)(blk*16 + i)*DIN + f);
    }
    __syncthreads();
    #pragma unroll 4
    for (int ib = 0; ib < 16; ++ib){
      int i = blk*16 + ib;
      u64 cc[4];
      #pragma unroll
      for (int p = 0; p < 4; ++p)
        cc[p] = *(const u64*)&c_s[i*CPAD + n0 + p*2];   // warp-uniform bcast
      #pragma unroll
      for (int j = 0; j < 8; ++j){
        u64 ud = dup2(u_s[ib*DIN + h*256 + j*32 + l]);
        #pragma unroll
        for (int p = 0; p < 4; ++p) acc[p][j] = fma2(cc[p], ud, acc[p][j]);
      }
    }
  }
  float* sp = g_spart + ((size_t)(ic*BATCH + b)*NC)*DIN;
  #pragma unroll
  for (int p = 0; p < 4; ++p)
    #pragma unroll
    for (int j = 0; j < 8; ++j){
      float lo, hi; unpk2(acc[p][j], lo, hi);
      int k = h*256 + j*32 + l;
      sp[(size_t)(n0+2*p  )*DIN + k] = lo;
      sp[(size_t)(n0+2*p+1)*DIN + k] = hi;
    }
}

// --------------------------------------------------------------------------
extern "C" void kernel_launch(void* const* d_in, const int* in_sizes, int n_in,
                              void* d_out, int out_size){
  const float* u = (const float*)d_in[0];   // [64,1024,512]
  const float* W = (const float*)d_in[1];   // [1,512,2048]
  float* out = (float*)d_out;               // [64,32,64]
  (void)in_sizes; (void)n_in; (void)out_size;

  cudaFuncSetAttribute(outv_kernel,
                       cudaFuncAttributeMaxDynamicSharedMemorySize, OUTV_SMEM);
  cudaFuncSetAttribute(accum_kernel,
                       cudaFuncAttributeMaxDynamicSharedMemorySize, ACC_SMEM);

  // iter 0: uniform coupling
  colsum_kernel<<<dim3(BATCH, ICN), 512>>>(u);
  outv_kernel<<<dim3(NC, NBG), 512, OUTV_SMEM>>>(W, 0, 1, nullptr);

  // iter 1
  logits_kernel<<<dim3(BATCH, ICN), 256>>>(u);
  accum_kernel<<<dim3(BATCH, ICN), 256, ACC_SMEM>>>(u);
  outv_kernel<<<dim3(NC, NBG), 512, OUTV_SMEM>>>(W, 1, 1, nullptr);

  // iter 2 (final)
  logits_kernel<<<dim3(BATCH, ICN), 256>>>(u);
  accum_kernel<<<dim3(BATCH, ICN), 256, ACC_SMEM>>>(u);
  outv_kernel<<<dim3(NC, NBG), 512, OUTV_SMEM>>>(W, 1, 0, out);
}